// round 1
// baseline (speedup 1.0000x reference)
#include <cuda_runtime.h>
#include <math.h>

// BernsteinNetwork: N=32768, D=8, ORDER=24, P=32
#define NSAMP 32768
#define DDIM  8
#define PPERM 32
#define KK    25
#define PAD   28   // padded row stride (floats) -> 112B rows, 16B aligned

typedef unsigned long long u64;

// ---------------- scratch (no allocation allowed) ----------------
__device__ float g_sc2[25];
__device__ float g_wv [7 * 32 * 625];   // exp(varw_rest) * sc2[j]
__device__ float g_wv0[32 * 25];        // exp(varw0)     * sc2[k]
__device__ float g_pm[PPERM * NSAMP];
__device__ float g_pv[PPERM * NSAMP];

__device__ __constant__ double BINOM_D[25] = {
    1.0, 24.0, 276.0, 2024.0, 10626.0, 42504.0, 134596.0, 346104.0,
    735471.0, 1307504.0, 1961256.0, 2496144.0, 2704156.0, 2496144.0,
    1961256.0, 1307504.0, 735471.0, 346104.0, 134596.0, 42504.0,
    10626.0, 2024.0, 276.0, 24.0, 1.0};

// ---------------- f32x2 packed helpers (sm_100+) ----------------
__device__ __forceinline__ u64 pack2(float a) {
    u64 r; asm("mov.b64 %0, {%1, %1};" : "=l"(r) : "f"(a)); return r;
}
__device__ __forceinline__ u64 mul2(u64 a, u64 b) {
    u64 d; asm("mul.rn.f32x2 %0, %1, %2;" : "=l"(d) : "l"(a), "l"(b)); return d;
}
__device__ __forceinline__ void fma2(u64& d, u64 a, u64 b) {
    asm("fma.rn.f32x2 %0, %1, %2, %0;" : "+l"(d) : "l"(a), "l"(b));
}
__device__ __forceinline__ void unpack2(u64 v, float& lo, float& hi) {
    asm("mov.b64 {%0, %1}, %2;" : "=f"(lo), "=f"(hi) : "l"(v));
}

// dst[j] = sum_k src[k] * W[k*PAD + j], W in shared, rows 16B aligned.
__device__ __forceinline__ void matvec25(const float src[25], const float* W, float dst[25]) {
    u64 acc[12]; float a24;
    {
        u64 a2 = pack2(src[0]);
        const u64* row = reinterpret_cast<const u64*>(W);
        #pragma unroll
        for (int jj = 0; jj < 12; jj++) acc[jj] = mul2(a2, row[jj]);
        a24 = src[0] * W[24];
    }
    #pragma unroll
    for (int k = 1; k < 25; k++) {
        u64 a2 = pack2(src[k]);
        const u64* row = reinterpret_cast<const u64*>(W + k * PAD);
        #pragma unroll
        for (int jj = 0; jj < 12; jj++) fma2(acc[jj], a2, row[jj]);
        a24 = fmaf(src[k], W[k * PAD + 24], a24);
    }
    #pragma unroll
    for (int jj = 0; jj < 12; jj++) unpack2(acc[jj], dst[2 * jj], dst[2 * jj + 1]);
    dst[24] = a24;
}

// ---------------- setup: sc2 = solve( (B(I)^2) x = 1 ) ----------------
// M built with f32 rounding at each step to mirror the reference's float32
// pipeline (incl. underflow of squared tiny entries), solved in double via
// Gauss-Jordan with partial pivoting.
__global__ void k_sc2() {
    __shared__ double A[25][26];
    __shared__ int piv;
    int t = threadIdx.x;
    if (t < 25) {
        float ti = (float)t / 24.0f;
        float om = 1.0f - ti;
        for (int k = 0; k < 25; k++) {
            float xk = (float)pow((double)ti, (double)k);
            float ym = (float)pow((double)om, (double)(24 - k));
            float val = (xk * ym) * (float)BINOM_D[k];
            A[t][k] = (double)(val * val);
        }
        A[t][25] = 1.0;
    }
    __syncthreads();
    for (int k = 0; k < 25; k++) {
        if (t == 0) {
            int pi = k; double best = fabs(A[k][k]);
            for (int i = k + 1; i < 25; i++) {
                double v = fabs(A[i][k]);
                if (v > best) { best = v; pi = i; }
            }
            piv = pi;
        }
        __syncthreads();
        int pv = piv;
        if (pv != k && t < 26) { double tmp = A[k][t]; A[k][t] = A[pv][t]; A[pv][t] = tmp; }
        __syncthreads();
        if (t < 25 && t != k) {
            double f = A[t][k] / A[k][k];
            for (int j = k; j < 26; j++) A[t][j] -= f * A[k][j];
        }
        __syncthreads();
    }
    if (t < 25) g_sc2[t] = (float)(A[t][25] / A[t][t]);
}

// ---------------- setup: variance weights = exp(varw) * sc2 ----------------
__global__ void k_prep(const float* __restrict__ vr, const float* __restrict__ v0) {
    int i = blockIdx.x * blockDim.x + threadIdx.x;
    if (i < 7 * 32 * 625) {
        g_wv[i] = expf(vr[i]) * g_sc2[i % 25];
    } else if (i < 7 * 32 * 625 + 32 * 25) {
        int r = i - 7 * 32 * 625;
        g_wv0[r] = expf(v0[r]) * g_sc2[r % 25];
    }
}

// ---------------- main: one thread = one (sample, perm) ----------------
__global__ void __launch_bounds__(256, 2) k_main(
    const float* __restrict__ X, const int* __restrict__ perm,
    const float* __restrict__ wm0, const float* __restrict__ wmr,
    const float* __restrict__ pprec)
{
    __shared__ __align__(16) float sWm[7][25][PAD];
    __shared__ __align__(16) float sWv[7][25][PAD];
    __shared__ float s0m[25], s0v[25];
    __shared__ int sperm[8];

    int p = blockIdx.y;
    int tid = threadIdx.x;

    for (int e = tid; e < 7 * 625; e += 256) {
        int l = e / 625; int r = e - l * 625;
        int k = r / 25;  int j = r - k * 25;
        sWm[l][k][j] = wmr[(l * 32 + p) * 625 + r];
        sWv[l][k][j] = g_wv[(l * 32 + p) * 625 + r];
    }
    if (tid < 25) { s0m[tid] = wm0[p * 25 + tid]; s0v[tid] = g_wv0[p * 25 + tid]; }
    if (tid < 8)  { sperm[tid] = perm[p * 8 + tid]; }
    __syncthreads();

    const float BIN[25] = {
        1.f, 24.f, 276.f, 2024.f, 10626.f, 42504.f, 134596.f, 346104.f,
        735471.f, 1307504.f, 1961256.f, 2496144.f, 2704156.f, 2496144.f,
        1961256.f, 1307504.f, 735471.f, 346104.f, 134596.f, 42504.f,
        10626.f, 2024.f, 276.f, 24.f, 1.f};

    int n = blockIdx.x * 256 + tid;
    const float* xr = X + n * DDIM;

    float fm[25], fv[25];
    // level 0: fm = meanw0 * Bi, fv = (exp(varw0)*sc2) * Bi^2
    {
        float u = xr[sperm[0]];
        float xp = 1.f;
        #pragma unroll
        for (int j = 0; j < 25; j++) {
            float c = BIN[j] * xp;
            fm[j] = s0m[j] * c;
            fv[j] = s0v[j] * (c * c);
            xp *= u;
        }
        float v = 1.f - u, yp = 1.f, yp2 = 1.f, vv = v * v;
        #pragma unroll
        for (int j = 24; j >= 0; j--) {
            fm[j] *= yp; fv[j] *= yp2;
            yp *= v; yp2 *= vv;
        }
    }

    // levels 1..7
    #pragma unroll 1
    for (int l = 0; l < 7; l++) {
        float u = xr[sperm[l + 1]];
        float t[25];

        matvec25(fm, &sWm[l][0][0], t);
        float xp = 1.f;
        #pragma unroll
        for (int j = 0; j < 25; j++) { fm[j] = t[j] * (BIN[j] * xp); xp *= u; }
        float v = 1.f - u, yp = 1.f;
        #pragma unroll
        for (int j = 24; j >= 0; j--) { fm[j] *= yp; yp *= v; }

        matvec25(fv, &sWv[l][0][0], t);
        xp = 1.f;
        #pragma unroll
        for (int j = 0; j < 25; j++) { float c = BIN[j] * xp; fv[j] = t[j] * (c * c); xp *= u; }
        float vv = v * v; yp = 1.f;
        #pragma unroll
        for (int j = 24; j >= 0; j--) { fv[j] *= yp; yp *= vv; }
    }

    float sm = 0.f, sv = 0.f;
    #pragma unroll
    for (int j = 0; j < 25; j++) { sm += fm[j]; sv += fv[j]; }
    g_pm[p * NSAMP + n] = sm;
    g_pv[p * NSAMP + n] = sv / pprec[p];
}

// ---------------- deterministic reduction over permutations ----------------
__global__ void k_reduce(float* __restrict__ out) {
    int n = blockIdx.x * blockDim.x + threadIdx.x;
    float sm = 0.f, sv = 0.f;
    #pragma unroll
    for (int p = 0; p < PPERM; p++) {
        sm += g_pm[p * NSAMP + n];
        sv += g_pv[p * NSAMP + n];
    }
    out[2 * n]     = sm;
    out[2 * n + 1] = sv;
}

extern "C" void kernel_launch(void* const* d_in, const int* in_sizes, int n_in,
                              void* d_out, int out_size) {
    const float* X    = (const float*)d_in[0];
    const int*   perm = (const int*)  d_in[1];
    const float* wm0  = (const float*)d_in[2];
    const float* wmr  = (const float*)d_in[3];
    const float* wv0  = (const float*)d_in[4];
    const float* wvr  = (const float*)d_in[5];
    const float* pp   = (const float*)d_in[6];

    k_sc2<<<1, 32>>>();
    k_prep<<<(7 * 32 * 625 + 32 * 25 + 255) / 256, 256>>>(wvr, wv0);
    k_main<<<dim3(NSAMP / 256, PPERM), 256>>>(X, perm, wm0, wmr, pp);
    k_reduce<<<NSAMP / 256, 256>>>((float*)d_out);
}

// round 2
// speedup vs baseline: 1.0045x; 1.0045x over previous
#include <cuda_runtime.h>
#include <math.h>

// BernsteinNetwork: N=32768, D=8, ORDER=24, P=32
#define NSAMP 32768
#define PPERM 32

typedef unsigned long long u64;

// ---------------- scratch (no device allocation allowed) ----------------
__device__ float g_sc2[25];
__device__ __align__(16) u64 g_W [PPERM * 7 * 25 * 26]; // packed (Wm*C[j], exp(Wv)*sc2[j]*C[j]^2), j padded to 26
__device__ u64 g_W0[PPERM * 25];
__device__ float g_pm[PPERM * NSAMP];
__device__ float g_pv[PPERM * NSAMP];

__device__ __constant__ float BINC[25] = {
    1.f, 24.f, 276.f, 2024.f, 10626.f, 42504.f, 134596.f, 346104.f,
    735471.f, 1307504.f, 1961256.f, 2496144.f, 2704156.f, 2496144.f,
    1961256.f, 1307504.f, 735471.f, 346104.f, 134596.f, 42504.f,
    10626.f, 2024.f, 276.f, 24.f, 1.f};

// ---------------- f32x2 packed helpers (sm_100) ----------------
__device__ __forceinline__ u64 mul2(u64 a, u64 b) {
    u64 d; asm("mul.rn.f32x2 %0, %1, %2;" : "=l"(d) : "l"(a), "l"(b)); return d;
}
__device__ __forceinline__ void fma2(u64& d, u64 a, u64 b) {
    asm("fma.rn.f32x2 %0, %1, %2, %0;" : "+l"(d) : "l"(a), "l"(b));
}
__device__ __forceinline__ void add2(u64& d, u64 a) {
    asm("add.rn.f32x2 %0, %0, %1;" : "+l"(d) : "l"(a));
}
__device__ __forceinline__ u64 packf2(float lo, float hi) {
    u64 r; asm("mov.b64 %0, {%1, %2};" : "=l"(r) : "f"(lo), "f"(hi)); return r;
}
__device__ __forceinline__ void unpackf2(u64 v, float& lo, float& hi) {
    asm("mov.b64 {%0, %1}, %2;" : "=f"(lo), "=f"(hi) : "l"(v));
}
// one LDS.128 -> two u64 operands
__device__ __forceinline__ void lds2(u64& a, u64& b, unsigned addr) {
    asm("ld.shared.v2.u64 {%0, %1}, [%2];" : "=l"(a), "=l"(b) : "r"(addr));
}

// ---------------- setup: sc2 = solve( (B(I)^2) x = 1 ) ----------------
// Matrix entries built with f32 rounding to mirror the reference's float32
// pipeline (incl. underflow of tiny squared entries), solved in double.
__global__ void k_sc2() {
    __shared__ double A[25][26];
    __shared__ int piv;
    int t = threadIdx.x;
    if (t < 25) {
        float ti = (float)t / 24.0f;
        float om = 1.0f - ti;
        for (int k = 0; k < 25; k++) {
            float xk = (float)pow((double)ti, (double)k);
            float ym = (float)pow((double)om, (double)(24 - k));
            float val = (xk * ym) * BINC[k];
            A[t][k] = (double)(val * val);
        }
        A[t][25] = 1.0;
    }
    __syncthreads();
    for (int k = 0; k < 25; k++) {
        if (t == 0) {
            int pi = k; double best = fabs(A[k][k]);
            for (int i = k + 1; i < 25; i++) {
                double v = fabs(A[i][k]);
                if (v > best) { best = v; pi = i; }
            }
            piv = pi;
        }
        __syncthreads();
        int pv = piv;
        if (pv != k && t < 26) { double tmp = A[k][t]; A[k][t] = A[pv][t]; A[pv][t] = tmp; }
        __syncthreads();
        if (t < 25 && t != k) {
            double f = A[t][k] / A[k][k];
            for (int j = k; j < 26; j++) A[t][j] -= f * A[k][j];
        }
        __syncthreads();
    }
    if (t < 25) g_sc2[t] = (float)(A[t][25] / A[t][t]);
}

// ---------------- prep: build interleaved, binomial-folded weights ----------------
// g_W layout: [p][l][k][j<26] of u64 pairs (mean, var), pad j=25 zeroed.
__global__ void k_prep(const float* __restrict__ wmr, const float* __restrict__ wvr,
                       const float* __restrict__ wm0, const float* __restrict__ wv0) {
    const int NW = PPERM * 7 * 25 * 26;
    int i = blockIdx.x * blockDim.x + threadIdx.x;
    if (i < NW) {
        int p = i / 4550;  int r  = i - p * 4550;
        int l = r / 650;   int rr = r - l * 650;
        int k = rr / 26;   int j  = rr - k * 26;
        u64 v = 0;
        if (j < 25) {
            int src = ((l * 32 + p) * 25 + k) * 25 + j;
            float b  = BINC[j];
            float lo = wmr[src] * b;
            float hi = expf(wvr[src]) * g_sc2[j] * b * b;
            v = ((u64)__float_as_uint(hi) << 32) | (u64)__float_as_uint(lo);
        }
        g_W[i] = v;
    } else if (i < NW + PPERM * 25) {
        int r = i - NW; int p = r / 25; int j = r - p * 25;
        float b  = BINC[j];
        float lo = wm0[p * 25 + j] * b;
        float hi = expf(wv0[p * 25 + j]) * g_sc2[j] * b * b;
        g_W0[r] = ((u64)__float_as_uint(hi) << 32) | (u64)__float_as_uint(lo);
    }
}

// ---------------- main: one thread = one (sample, perm) ----------------
__global__ void __launch_bounds__(256, 1) k_main(
    const float* __restrict__ X, const int* __restrict__ perm,
    const float* __restrict__ pprec)
{
    __shared__ __align__(16) u64 sW[7 * 25 * 26];   // 36400 B
    __shared__ u64 s0[25];
    __shared__ int sperm[8];

    int p = blockIdx.y;
    int tid = threadIdx.x;

    // straight float4 memcpy of this perm's weights (prep wrote final layout)
    {
        const float4* src4 = (const float4*)(g_W + p * 4550);
        float4* dst4 = (float4*)sW;
        #pragma unroll
        for (int i = 0; i < 2275; i += 256) {
            int e = i + tid;
            if (e < 2275) dst4[e] = src4[e];
        }
    }
    if (tid < 25) s0[tid] = g_W0[p * 25 + tid];
    if (tid < 8)  sperm[tid] = perm[p * 8 + tid];
    __syncthreads();

    int n = blockIdx.x * 256 + tid;
    const float* xr = X + n * 8;

    u64 f[25];   // packed (fm, fv)

    // level 0: f[j] = (wm0*C, wv0pre*C^2)[j] * (s, s^2),  s = u^j (1-u)^(24-j)
    {
        float u = __ldg(xr + sperm[0]);
        float om = 1.0f - u;
        float s[25]; float xp = 1.0f;
        #pragma unroll
        for (int j = 0; j < 25; j++) { s[j] = xp; xp *= u; }
        float yp = 1.0f;
        #pragma unroll
        for (int j = 24; j >= 0; j--) {
            float b = s[j] * yp;
            f[j] = mul2(s0[j], packf2(b, b * b));
            yp *= om;
        }
    }

    unsigned wbase = (unsigned)__cvta_generic_to_shared(sW);

    #pragma unroll 1
    for (int l = 0; l < 7; l++) {
        unsigned rowa = wbase + (unsigned)(l * 650 * 8);
        u64 a[25];
        {   // k = 0 : init accumulators
            u64 w[26];
            #pragma unroll
            for (int q = 0; q < 13; q++) lds2(w[2 * q], w[2 * q + 1], rowa + q * 16);
            #pragma unroll
            for (int j = 0; j < 25; j++) a[j] = mul2(f[0], w[j]);
        }
        #pragma unroll
        for (int k = 1; k < 25; k++) {
            unsigned ra = rowa + (unsigned)(k * 208);
            u64 w[26];
            #pragma unroll
            for (int q = 0; q < 13; q++) lds2(w[2 * q], w[2 * q + 1], ra + q * 16);
            #pragma unroll
            for (int j = 0; j < 25; j++) fma2(a[j], f[k], w[j]);
        }
        // epilogue: f[j] = a[j] * (s, s^2),  s = u^j (1-u)^(24-j)
        float u = __ldg(xr + sperm[l + 1]);
        float om = 1.0f - u;
        float s[25]; float xp = 1.0f;
        #pragma unroll
        for (int j = 0; j < 25; j++) { s[j] = xp; xp *= u; }
        float yp = 1.0f;
        #pragma unroll
        for (int j = 24; j >= 0; j--) {
            float b = s[j] * yp;
            f[j] = mul2(a[j], packf2(b, b * b));
            yp *= om;
        }
    }

    // packed reduction over j for both outputs at once
    u64 t = f[0];
    #pragma unroll
    for (int j = 1; j < 25; j++) add2(t, f[j]);
    float sm, sv; unpackf2(t, sm, sv);

    g_pm[p * NSAMP + n] = sm;
    g_pv[p * NSAMP + n] = sv / __ldg(pprec + p);
}

// ---------------- deterministic reduction over permutations ----------------
__global__ void k_reduce(float* __restrict__ out) {
    int n = blockIdx.x * blockDim.x + threadIdx.x;
    float sm = 0.f, sv = 0.f;
    #pragma unroll
    for (int p = 0; p < PPERM; p++) {
        sm += g_pm[p * NSAMP + n];
        sv += g_pv[p * NSAMP + n];
    }
    out[2 * n]     = sm;
    out[2 * n + 1] = sv;
}

extern "C" void kernel_launch(void* const* d_in, const int* in_sizes, int n_in,
                              void* d_out, int out_size) {
    const float* X    = (const float*)d_in[0];
    const int*   perm = (const int*)  d_in[1];
    const float* wm0  = (const float*)d_in[2];
    const float* wmr  = (const float*)d_in[3];
    const float* wv0  = (const float*)d_in[4];
    const float* wvr  = (const float*)d_in[5];
    const float* pp   = (const float*)d_in[6];

    const int NPREP = PPERM * 7 * 25 * 26 + PPERM * 25;
    k_sc2<<<1, 32>>>();
    k_prep<<<(NPREP + 255) / 256, 256>>>(wmr, wvr, wm0, wv0);
    k_main<<<dim3(NSAMP / 256, PPERM), 256>>>(X, perm, pp);
    k_reduce<<<NSAMP / 256, 256>>>((float*)d_out);
}

// round 4
// speedup vs baseline: 1.0627x; 1.0579x over previous
#include <cuda_runtime.h>
#include <math.h>

// BernsteinNetwork: N=32768, D=8, ORDER=24, P=32
#define NSAMP 32768
#define PPERM 32

typedef unsigned long long u64;

// ---------------- scratch (no device allocation allowed) ----------------
__device__ float g_sc2[25];
__device__ __align__(16) u64 g_W [PPERM * 7 * 25 * 26]; // packed (Wm*C[j], exp(Wv)*sc2[j]*C[j]^2), j padded to 26
__device__ u64 g_W0[PPERM * 25];
__device__ float g_pm[PPERM * NSAMP];
__device__ float g_pv[PPERM * NSAMP];

__device__ __constant__ float BINC[25] = {
    1.f, 24.f, 276.f, 2024.f, 10626.f, 42504.f, 134596.f, 346104.f,
    735471.f, 1307504.f, 1961256.f, 2496144.f, 2704156.f, 2496144.f,
    1961256.f, 1307504.f, 735471.f, 346104.f, 134596.f, 42504.f,
    10626.f, 2024.f, 276.f, 24.f, 1.f};

// ---------------- f32x2 packed helpers (sm_100) ----------------
__device__ __forceinline__ u64 mul2(u64 a, u64 b) {
    u64 d; asm("mul.rn.f32x2 %0, %1, %2;" : "=l"(d) : "l"(a), "l"(b)); return d;
}
__device__ __forceinline__ void fma2(u64& d, u64 a, u64 b) {
    asm("fma.rn.f32x2 %0, %1, %2, %0;" : "+l"(d) : "l"(a), "l"(b));
}
__device__ __forceinline__ void add2(u64& d, u64 a) {
    asm("add.rn.f32x2 %0, %0, %1;" : "+l"(d) : "l"(a));
}
__device__ __forceinline__ u64 packf2(float lo, float hi) {
    u64 r; asm("mov.b64 %0, {%1, %2};" : "=l"(r) : "f"(lo), "f"(hi)); return r;
}
__device__ __forceinline__ void unpackf2(u64 v, float& lo, float& hi) {
    asm("mov.b64 {%0, %1}, %2;" : "=f"(lo), "=f"(hi) : "l"(v));
}
// one LDS.128 -> two u64 operands
__device__ __forceinline__ void lds2(u64& a, u64& b, unsigned addr) {
    asm("ld.shared.v2.u64 {%0, %1}, [%2];" : "=l"(a), "=l"(b) : "r"(addr));
}

// ---------------- setup: sc2 = solve( (B(I)^2) x = 1 ) ----------------
__global__ void k_sc2() {
    __shared__ double A[25][26];
    __shared__ int piv;
    int t = threadIdx.x;
    if (t < 25) {
        float ti = (float)t / 24.0f;
        float om = 1.0f - ti;
        for (int k = 0; k < 25; k++) {
            float xk = (float)pow((double)ti, (double)k);
            float ym = (float)pow((double)om, (double)(24 - k));
            float val = (xk * ym) * BINC[k];
            A[t][k] = (double)(val * val);
        }
        A[t][25] = 1.0;
    }
    __syncthreads();
    for (int k = 0; k < 25; k++) {
        if (t == 0) {
            int pi = k; double best = fabs(A[k][k]);
            for (int i = k + 1; i < 25; i++) {
                double v = fabs(A[i][k]);
                if (v > best) { best = v; pi = i; }
            }
            piv = pi;
        }
        __syncthreads();
        int pv = piv;
        if (pv != k && t < 26) { double tmp = A[k][t]; A[k][t] = A[pv][t]; A[pv][t] = tmp; }
        __syncthreads();
        if (t < 25 && t != k) {
            double f = A[t][k] / A[k][k];
            for (int j = k; j < 26; j++) A[t][j] -= f * A[k][j];
        }
        __syncthreads();
    }
    if (t < 25) g_sc2[t] = (float)(A[t][25] / A[t][t]);
}

// ---------------- prep: interleaved, binomial-folded weights ----------------
__global__ void k_prep(const float* __restrict__ wmr, const float* __restrict__ wvr,
                       const float* __restrict__ wm0, const float* __restrict__ wv0) {
    const int NW = PPERM * 7 * 25 * 26;
    int i = blockIdx.x * blockDim.x + threadIdx.x;
    if (i < NW) {
        int p = i / 4550;  int r  = i - p * 4550;
        int l = r / 650;   int rr = r - l * 650;
        int k = rr / 26;   int j  = rr - k * 26;
        u64 v = 0;
        if (j < 25) {
            int src = ((l * 32 + p) * 25 + k) * 25 + j;
            float b  = BINC[j];
            float lo = wmr[src] * b;
            float hi = expf(wvr[src]) * g_sc2[j] * b * b;
            v = ((u64)__float_as_uint(hi) << 32) | (u64)__float_as_uint(lo);
        }
        g_W[i] = v;
    } else if (i < NW + PPERM * 25) {
        int r = i - NW; int p = r / 25; int j = r - p * 25;
        float b  = BINC[j];
        float lo = wm0[p * 25 + j] * b;
        float hi = expf(wv0[p * 25 + j]) * g_sc2[j] * b * b;
        g_W0[r] = ((u64)__float_as_uint(hi) << 32) | (u64)__float_as_uint(lo);
    }
}

// ---------------- main: one thread = one (sample, perm) ----------------
// 128-reg cap -> 2 CTAs/SM -> 4 warps/SMSP. Weight rows streamed 16B at a
// time (no 52-reg row buffer); epilogue is two in-place packed sweeps.
__global__ void __launch_bounds__(256, 2) k_main(
    const float* __restrict__ X, const int* __restrict__ perm,
    const float* __restrict__ pprec)
{
    __shared__ __align__(16) u64 sW[7 * 25 * 26];   // 36400 B
    __shared__ u64 s0[25];
    __shared__ int sperm[8];

    int p = blockIdx.y;
    int tid = threadIdx.x;

    {
        const float4* src4 = (const float4*)(g_W + p * 4550);
        float4* dst4 = (float4*)sW;
        #pragma unroll
        for (int i = 0; i < 2275; i += 256) {
            int e = i + tid;
            if (e < 2275) dst4[e] = src4[e];
        }
    }
    if (tid < 25) s0[tid] = g_W0[p * 25 + tid];
    if (tid < 8)  sperm[tid] = perm[p * 8 + tid];
    __syncthreads();

    int n = blockIdx.x * 256 + tid;
    const float* xr = X + n * 8;

    u64 f[25];   // packed (fm, fv)

    // level 0: f[j] = W0pre[j] * (u^j, u^2j) * (om^(24-j), om^(2(24-j)))
    {
        float u = __ldg(xr + sperm[0]);
        float om = 1.0f - u;
        float xp = 1.0f;
        #pragma unroll
        for (int j = 0; j < 25; j++) { f[j] = mul2(s0[j], packf2(xp, xp * xp)); xp *= u; }
        float yp = 1.0f;
        #pragma unroll
        for (int j = 24; j >= 0; j--) { f[j] = mul2(f[j], packf2(yp, yp * yp)); yp *= om; }
    }

    unsigned wbase = (unsigned)__cvta_generic_to_shared(sW);

    #pragma unroll 1
    for (int l = 0; l < 7; l++) {
        unsigned rowa = wbase + (unsigned)(l * 650 * 8);
        u64 a[25];
        {   // k = 0 : init accumulators, streaming weights 16B at a time
            #pragma unroll
            for (int q = 0; q < 13; q++) {
                u64 w0, w1;
                lds2(w0, w1, rowa + q * 16);
                a[2 * q] = mul2(f[0], w0);
                if (q < 12) a[2 * q + 1] = mul2(f[0], w1);
            }
        }
        #pragma unroll
        for (int k = 1; k < 25; k++) {
            unsigned ra = rowa + (unsigned)(k * 208);
            #pragma unroll
            for (int q = 0; q < 13; q++) {
                u64 w0, w1;
                lds2(w0, w1, ra + q * 16);
                fma2(a[2 * q], f[k], w0);
                if (q < 12) fma2(a[2 * q + 1], f[k], w1);
            }
        }
        // epilogue: f[j] = a[j] * (u^j, u^2j) * (om^(24-j), om^(2(24-j)))
        float u = __ldg(xr + sperm[l + 1]);
        float om = 1.0f - u;
        float xp = 1.0f;
        #pragma unroll
        for (int j = 0; j < 25; j++) { a[j] = mul2(a[j], packf2(xp, xp * xp)); xp *= u; }
        float yp = 1.0f;
        #pragma unroll
        for (int j = 24; j >= 0; j--) { f[j] = mul2(a[j], packf2(yp, yp * yp)); yp *= om; }
    }

    u64 t = f[0];
    #pragma unroll
    for (int j = 1; j < 25; j++) add2(t, f[j]);
    float sm, sv; unpackf2(t, sm, sv);

    g_pm[p * NSAMP + n] = sm;
    g_pv[p * NSAMP + n] = sv / __ldg(pprec + p);
}

// ---------------- deterministic reduction over permutations ----------------
__global__ void k_reduce(float* __restrict__ out) {
    int n = blockIdx.x * blockDim.x + threadIdx.x;
    float sm = 0.f, sv = 0.f;
    #pragma unroll
    for (int p = 0; p < PPERM; p++) {
        sm += g_pm[p * NSAMP + n];
        sv += g_pv[p * NSAMP + n];
    }
    out[2 * n]     = sm;
    out[2 * n + 1] = sv;
}

extern "C" void kernel_launch(void* const* d_in, const int* in_sizes, int n_in,
                              void* d_out, int out_size) {
    const float* X    = (const float*)d_in[0];
    const int*   perm = (const int*)  d_in[1];
    const float* wm0  = (const float*)d_in[2];
    const float* wmr  = (const float*)d_in[3];
    const float* wv0  = (const float*)d_in[4];
    const float* wvr  = (const float*)d_in[5];
    const float* pp   = (const float*)d_in[6];

    const int NPREP = PPERM * 7 * 25 * 26 + PPERM * 25;
    k_sc2<<<1, 32>>>();
    k_prep<<<(NPREP + 255) / 256, 256>>>(wmr, wvr, wm0, wv0);
    k_main<<<dim3(NSAMP / 256, PPERM), 256>>>(X, perm, pp);
    k_reduce<<<NSAMP / 256, 256>>>((float*)d_out);
}